// round 16
// baseline (speedup 1.0000x reference)
#include <cuda_runtime.h>
#include <cstdint>

#define BB 8
#define NN 2048
#define IND 128
#define OUTD 64
#define NEG_SLOPE 0.2f

// Scratch (device globals)
__device__ float g_hp[BB * NN * OUTD];     // projected features [b][j][c]
__device__ float g_s[BB * NN];             // s_i + b_attn (natural units)
__device__ float g_d[BB * NN];             // d_j (natural units)
__device__ float g_dmax[BB];
__device__ float g_dsort[BB * NN];         // d sorted descending
__device__ int   g_perm[BB * NN];          // original j index per sorted rank
__device__ float g_P [BB * (NN + 1) * OUTD];  // prefix sums, branch e^{d-dmax}
__device__ float g_Q [BB * (NN + 1) * OUTD];  // suffix sums, branch e^{0.2(d-dmax)}
__device__ float g_P1[BB * (NN + 1)];         // ones-column (denominator) prefix
__device__ float g_Q1[BB * (NN + 1)];

#define KPROJ_SMEM_BYTES ((8192 + 16384 + 192) * 4)

// ---------- packed f32x2 helpers ----------
__device__ __forceinline__ unsigned long long fma2(unsigned long long a,
                                                   unsigned long long b,
                                                   unsigned long long c) {
    unsigned long long d;
    asm("fma.rn.f32x2 %0, %1, %2, %3;" : "=l"(d) : "l"(a), "l"(b), "l"(c));
    return d;
}
__device__ __forceinline__ unsigned long long pk2(float a, float b) {
    unsigned long long u;
    asm("mov.b64 %0, {%1, %2};" : "=l"(u) : "f"(a), "f"(b));
    return u;
}
__device__ __forceinline__ void upk2(unsigned long long u, float& lo, float& hi) {
    asm("mov.b64 {%0, %1}, %2;" : "=f"(lo), "=f"(hi) : "l"(u));
}

// ============================================================
// Kernel 1: hp = h@W + b ; s = hp@a_src + b_attn ; d = hp@a_dst
// 128 CTAs x 128 threads, 1 row/thread (proven 22.5us structure).
// ============================================================
__global__ __launch_bounds__(128) void k_proj(
    const float* __restrict__ h, const float* __restrict__ W,
    const float* __restrict__ bfc, const float* __restrict__ asrc,
    const float* __restrict__ adst, const float* __restrict__ battn) {
    extern __shared__ __align__(16) float dyn[];
    float* sW = dyn;                          // 32 KB
    float4* sh4 = (float4*)(dyn + 8192);      // 64 KB
    float* sb = dyn + 8192 + 16384;
    float* sas = sb + 64;
    float* sad = sb + 128;
    const int tid = threadIdx.x;

    for (int v = tid; v < IND * OUTD / 4; v += 128)
        ((float4*)sW)[v] = ((const float4*)W)[v];
    if (tid < OUTD) { sb[tid] = bfc[tid]; sas[tid] = asrc[tid]; sad[tid] = adst[tid]; }
    const float4* hg4 = (const float4*)(h + (size_t)blockIdx.x * 128 * IND);
#pragma unroll
    for (int v = 0; v < 32; v++) {
        int lin = v * 128 + tid, row = lin >> 5, k4 = lin & 31;
        sh4[row * 32 + (k4 ^ (row & 31))] = hg4[lin];
    }
    __syncthreads();

    const int row = blockIdx.x * 128 + tid;
    const int sw = tid & 31;
    unsigned long long acc[32];
#pragma unroll
    for (int i = 0; i < 32; i++) acc[i] = pk2(sb[2 * i], sb[2 * i + 1]);
#pragma unroll 4
    for (int k4 = 0; k4 < 32; k4++) {
        float4 hv = sh4[tid * 32 + (k4 ^ sw)];
        float hk[4] = {hv.x, hv.y, hv.z, hv.w};
#pragma unroll
        for (int kk = 0; kk < 4; kk++) {
            unsigned long long hh = pk2(hk[kk], hk[kk]);
            const ulonglong2* wr = (const ulonglong2*)(sW + (k4 * 4 + kk) * OUTD);
#pragma unroll
            for (int q = 0; q < 16; q++) {
                ulonglong2 wv = wr[q];
                acc[2 * q] = fma2(hh, wv.x, acc[2 * q]);
                acc[2 * q + 1] = fma2(hh, wv.y, acc[2 * q + 1]);
            }
        }
    }
    float o[64];
#pragma unroll
    for (int i = 0; i < 32; i++) upk2(acc[i], o[2 * i], o[2 * i + 1]);

    float s = 0.f, d = 0.f;
#pragma unroll
    for (int c = 0; c < OUTD; c++) { s = fmaf(o[c], sas[c], s); d = fmaf(o[c], sad[c], d); }
    g_s[row] = s + battn[0];
    g_d[row] = d;

    float4* dst = (float4*)(g_hp + (size_t)row * OUTD);
#pragma unroll
    for (int q = 0; q < 16; q++)
        dst[q] = make_float4(o[4 * q], o[4 * q + 1], o[4 * q + 2], o[4 * q + 3]);
}

// ============================================================
// Kernel 2: per-batch max of d
// ============================================================
__global__ void k_dmax() {
    __shared__ float sm[256];
    int b = blockIdx.x, tid = threadIdx.x;
    float m = -1e30f;
    for (int j = tid; j < NN; j += 256) m = fmaxf(m, g_d[b * NN + j]);
    sm[tid] = m; __syncthreads();
    for (int off = 128; off > 0; off >>= 1) {
        if (tid < off) sm[tid] = fmaxf(sm[tid], sm[tid + off]);
        __syncthreads();
    }
    if (tid == 0) g_dmax[b] = sm[0];
}

// ============================================================
// Kernel 3: bitonic sort of d per batch (descending), with permutation.
// grid 8, block 1024, 2048 elements in smem.
// ============================================================
__global__ __launch_bounds__(1024) void k_sort() {
    __shared__ float key[NN];
    __shared__ int val[NN];
    const int b = blockIdx.x, tid = threadIdx.x;
    for (int i = tid; i < NN; i += 1024) { key[i] = g_d[b * NN + i]; val[i] = i; }
    __syncthreads();
    for (int k = 2; k <= NN; k <<= 1) {
        for (int j = k >> 1; j > 0; j >>= 1) {
            for (int i = tid; i < NN; i += 1024) {
                int ixj = i ^ j;
                if (ixj > i) {
                    bool up = ((i & k) == 0);   // descending overall
                    float a = key[i], c = key[ixj];
                    if (up ? (a < c) : (a > c)) {
                        key[i] = c; key[ixj] = a;
                        int t = val[i]; val[i] = val[ixj]; val[ixj] = t;
                    }
                }
            }
            __syncthreads();
        }
    }
    for (int i = tid; i < NN; i += 1024) {
        g_dsort[b * NN + i] = key[i];
        g_perm[b * NN + i] = val[i];
    }
}

// ============================================================
// Kernel 4: blocked scans. grid (8 batches, 2 branches), block 1024.
// branch 0: P[k] = sum_{rank<k} e^{d-dmax} * [hp | 1], forward order.
// branch 1: Q[k] = sum_{rank>=k} e^{0.2(d-dmax)} * [hp | 1], reverse order.
// 32 chunks x 65 cols = 2080 tasks; 2-pass (chunk sums, then replay).
// ============================================================
__global__ __launch_bounds__(1024) void k_scan() {
    __shared__ float ews[NN];       // weights in scan order
    __shared__ int sperm[NN];       // hp row in scan order
    __shared__ float csum[32 * 65];
    const int b = blockIdx.x, br = blockIdx.y, tid = threadIdx.x;
    const float dmax = g_dmax[b];

    for (int i = tid; i < NN; i += 1024) {
        int r = br ? (NN - 1 - i) : i;
        float dd = g_dsort[b * NN + r] - dmax;
        ews[i] = __expf(br ? NEG_SLOPE * dd : dd);
        sperm[i] = g_perm[b * NN + r];
    }
    __syncthreads();

    const float* __restrict__ hpB = g_hp + (size_t)b * NN * OUTD;
    // pass 1: chunk sums
    for (int t = tid; t < 32 * 65; t += 1024) {
        int chunk = t / 65, c = t % 65, base = chunk * 64;
        float ssum = 0.f;
        for (int r = 0; r < 64; r++) {
            float x = (c < 64) ? hpB[(size_t)sperm[base + r] * OUTD + c] : 1.0f;
            ssum = fmaf(ews[base + r], x, ssum);
        }
        csum[chunk * 65 + c] = ssum;
    }
    __syncthreads();
    // pass 2: replay with running prefix, write to global
    for (int t = tid; t < 32 * 65; t += 1024) {
        int chunk = t / 65, c = t % 65, base = chunk * 64;
        float run = 0.f;
        for (int cc = 0; cc < chunk; cc++) run += csum[cc * 65 + c];
        for (int r = 0; r < 64; r++) {
            int sr = base + r;
            float x = (c < 64) ? hpB[(size_t)sperm[sr] * OUTD + c] : 1.0f;
            run = fmaf(ews[sr], x, run);
            int widx = br ? (NN - 1 - sr) : (sr + 1);
            size_t off = (size_t)b * (NN + 1) + widx;
            if (br) { if (c < 64) g_Q[off * OUTD + c] = run; else g_Q1[off] = run; }
            else    { if (c < 64) g_P[off * OUTD + c] = run; else g_P1[off] = run; }
        }
    }
    // boundary zeros
    if (tid < 65) {
        size_t off = (size_t)b * (NN + 1) + (br ? NN : 0);
        if (br) { if (tid < 64) g_Q[off * OUTD + tid] = 0.f; else g_Q1[off] = 0.f; }
        else    { if (tid < 64) g_P[off * OUTD + tid] = 0.f; else g_P1[off] = 0.f; }
    }
}

// ============================================================
// Kernel 5: per-row binary search + combine + softmax-normalize + ELU.
// grid (8, 8), block 256 (one row per thread).
// ============================================================
__global__ __launch_bounds__(256) void k_out(float* __restrict__ out) {
    __shared__ float sd[NN];
    const int b = blockIdx.x;
    const int i = blockIdx.y * 256 + threadIdx.x;
    for (int t = threadIdx.x; t < NN; t += 256) sd[t] = g_dsort[b * NN + t];
    __syncthreads();

    const float s = g_s[b * NN + i];
    const float th = -s;
    int lo = 0, hi = NN;
    while (lo < hi) {
        int mid = (lo + hi) >> 1;
        if (sd[mid] >= th) lo = mid + 1; else hi = mid;
    }
    const int k = lo;   // #{j : d_j >= -s_i} = positive-branch count

    const float tmax = s + g_dmax[b];
    const float mi = fmaxf(tmax, NEG_SLOPE * tmax);
    const float alpha = __expf(tmax - mi);
    const float beta = __expf(NEG_SLOPE * tmax - mi);

    const size_t off = (size_t)b * (NN + 1) + k;
    const float denom = alpha * g_P1[off] + beta * g_Q1[off];
    const float inv = 1.0f / denom;

    const float4* pP = (const float4*)(g_P + off * OUTD);
    const float4* pQ = (const float4*)(g_Q + off * OUTD);
    float4* dst = (float4*)(out + ((size_t)b * NN + i) * OUTD);
#pragma unroll
    for (int q = 0; q < 16; q++) {
        float4 pv = pP[q], qv = pQ[q], ov;
        float v;
        v = (alpha * pv.x + beta * qv.x) * inv; ov.x = v > 0.f ? v : (__expf(v) - 1.0f);
        v = (alpha * pv.y + beta * qv.y) * inv; ov.y = v > 0.f ? v : (__expf(v) - 1.0f);
        v = (alpha * pv.z + beta * qv.z) * inv; ov.z = v > 0.f ? v : (__expf(v) - 1.0f);
        v = (alpha * pv.w + beta * qv.w) * inv; ov.w = v > 0.f ? v : (__expf(v) - 1.0f);
        dst[q] = ov;
    }
}

extern "C" void kernel_launch(void* const* d_in, const int* in_sizes, int n_in,
                              void* d_out, int out_size) {
    const float* h = (const float*)d_in[0];
    const float* W = (const float*)d_in[1];
    const float* bfc = (const float*)d_in[2];
    const float* asrc = (const float*)d_in[3];
    const float* adst = (const float*)d_in[4];
    const float* battn = (const float*)d_in[5];
    float* out = (float*)d_out;

    cudaFuncSetAttribute(k_proj, cudaFuncAttributeMaxDynamicSharedMemorySize,
                         KPROJ_SMEM_BYTES);

    k_proj<<<BB * NN / 128, 128, KPROJ_SMEM_BYTES>>>(h, W, bfc, asrc, adst, battn);
    k_dmax<<<BB, 256>>>();
    k_sort<<<BB, 1024>>>();
    k_scan<<<dim3(BB, 2), 1024>>>();
    k_out<<<dim3(BB, NN / 256), 256>>>(out);
}